// round 11
// baseline (speedup 1.0000x reference)
#include <cuda_runtime.h>
#include <cstdint>

#define Bdim 32
#define Kdim 17
#define Hdim 160
#define Wdim 160
#define HW   (Hdim*Wdim)
#define NG   (HW/4)
#define Pn   30
#define Sn   10
#define Ln   19
#define NCH  (Bdim*Kdim)
#define NBL  (Bdim*Ln)
#define T1   320
#define NWARP (T1/32)
#define NSTRIP 20
#define SPX   8
#define RPB   10
#define SEG   384
#define T2   512
#define GRID2 148
#define NBINS 1024
#define SCAP  256
#define NEGF  (-1.0e30f)

__constant__ int c_skel_a[Ln] = {15,13,16,14,11, 5, 6, 5, 5, 6, 7, 8, 1, 0, 0, 1, 2, 3, 4};
__constant__ int c_skel_b[Ln] = {13,11,14,12,12,11,12, 6, 7, 8, 9,10, 2, 1, 2, 3, 4, 5, 6};

// ---------------- cp.async helpers ----------------
__device__ __forceinline__ void cp16(void* s, const void* g) {
    unsigned sa = (unsigned)__cvta_generic_to_shared(s);
    asm volatile("cp.async.cg.shared.global [%0], [%1], 16;\n" :: "r"(sa), "l"(g));
}
__device__ __forceinline__ void cp_commit() { asm volatile("cp.async.commit_group;\n"); }
template <int N>
__device__ __forceinline__ void cp_wait() { asm volatile("cp.async.wait_group %0;\n" :: "n"(N)); }

// monotone bin: v = h^9 (uniform-izes max-of-9 peak-score distribution)
__device__ __forceinline__ int bin_of(float h) {
    float h2 = h * h;
    float h4 = h2 * h2;
    float v  = h4 * h4 * h;
    int b = (int)(v * (float)NBINS);
    return b < 0 ? 0 : (b > NBINS - 1 ? NBINS - 1 : b);
}

__device__ __forceinline__ float max3(float a, float b, float c) {
    return fmaxf(fmaxf(a, b), c);
}

// load one row of an 8px strip: 2 contiguous float4 + 2 edge scalars.
__device__ __forceinline__ void loadrow8(const float* __restrict__ hp,
                                         int y, int x0, bool lf, bool rt,
                                         float rm[8], float px[8])
{
    if (y < 0 || y >= Hdim) {
        #pragma unroll
        for (int j = 0; j < SPX; ++j) { rm[j] = NEGF; px[j] = NEGF; }
        return;
    }
    const float4* p4 = (const float4*)(hp + y * Wdim + x0);
    float4 A = __ldg(p4);
    float4 B = __ldg(p4 + 1);
    float w[SPX + 2];
    w[0] = lf ? __ldg(hp + y * Wdim + x0 - 1) : NEGF;
    w[1] = A.x; w[2] = A.y; w[3] = A.z; w[4] = A.w;
    w[5] = B.x; w[6] = B.y; w[7] = B.z; w[8] = B.w;
    w[9] = rt ? __ldg(hp + y * Wdim + x0 + SPX) : NEGF;
    #pragma unroll
    for (int j = 0; j < SPX; ++j) {
        px[j] = w[j + 1];
        rm[j] = max3(w[j], w[j + 1], w[j + 2]);
    }
}

// ---------------------------------------------------------------------------
// Stage 1: one block per (b,k) channel.  Strip sweep + per-warp segmented
// candidate lists (kills single-address ATOMS serialization), histogram
// radix-select, warp argmax, subpixel refine.
// ---------------------------------------------------------------------------
__global__ void __launch_bounds__(T1) stage1_kernel(const float* __restrict__ heat,
                                                    float* __restrict__ out_peaks)
{
    if (threadIdx.x == 0) cudaTriggerProgrammaticLaunchCompletion();

    __shared__ unsigned long long list[NWARP * SEG];
    __shared__ int wcnt[NWARP];
    __shared__ unsigned hist[NBINS];
    __shared__ unsigned long long surv[SCAP];
    __shared__ unsigned long long s_top[Pn];
    __shared__ int s_sc, s_cut;

    const int ch = blockIdx.x;
    const float* hp = heat + (size_t)ch * HW;
    const int tid = threadIdx.x;
    const int wid = tid >> 5;
    const int lane = tid & 31;

    for (int i = tid; i < NBINS; i += T1) hist[i] = 0;
    if (tid < NWARP) wcnt[tid] = 0;
    if (tid == 0) { s_sc = 0; s_cut = 0; }
    __syncthreads();

    // ---- pass 1: strip sweep (20 strips x 16 bands, 8px x 10row strips) ----
    const int strip = tid % NSTRIP;
    const int band  = tid / NSTRIP;
    const int x0 = strip * SPX;
    const int y0 = band * RPB;
    const bool lf = (strip > 0);
    const bool rt = (strip < NSTRIP - 1);

    float rmU[SPX], rmC[SPX], rmD[SPX];
    float C8[SPX], D8[SPX];

    loadrow8(hp, y0 - 1, x0, lf, rt, rmU, D8);
    loadrow8(hp, y0,     x0, lf, rt, rmC, C8);

    #pragma unroll 2
    for (int r = 0; r < RPB; ++r) {
        const int y = y0 + r;
        loadrow8(hp, y + 1, x0, lf, rt, rmD, D8);
        #pragma unroll
        for (int j = 0; j < SPX; ++j) {
            float h = C8[j];
            if (h > 0.1f && h >= rmU[j] && h >= rmC[j] && h >= rmD[j]) {
                int pos = atomicAdd(&wcnt[wid], 1);
                if (pos < SEG) {
                    unsigned idx = (unsigned)(y * Wdim + x0 + j);
                    list[wid * SEG + pos] = ((unsigned long long)__float_as_uint(h) << 32) |
                                            (unsigned long long)(0xFFFFFFFFu - idx);
                }
            }
        }
        #pragma unroll
        for (int j = 0; j < SPX; ++j) {
            rmU[j] = rmC[j]; rmC[j] = rmD[j]; C8[j] = D8[j];
        }
    }
    __syncthreads();

    // ---- histogram over segmented candidate lists ----
    for (int i = tid; i < NWARP * SEG; i += T1) {
        int w = i / SEG;
        int o = i - w * SEG;
        int c = wcnt[w]; c = (c < SEG) ? c : SEG;
        if (o < c) {
            float h = __uint_as_float((unsigned)(list[i] >> 32));
            atomicAdd(&hist[bin_of(h)], 1u);
        }
    }
    __syncthreads();

    // ---- warp 0: cutoff bin = highest bin whose suffix count >= Pn ----
    if (tid < 32) {
        int acc = 0, cut = 0;
        for (int base = NBINS - 32; base >= 0; base -= 32) {
            int s = (int)hist[base + lane];
            #pragma unroll
            for (int off = 1; off < 32; off <<= 1) {
                int t = __shfl_down_sync(0xffffffffu, s, off);
                if (lane + off < 32) s += t;
            }
            int chunk_total = __shfl_sync(0xffffffffu, s, 0);
            if (acc + chunk_total >= Pn) {
                unsigned msk = __ballot_sync(0xffffffffu, acc + s >= Pn);
                cut = base + (31 - __clz(msk));
                break;
            }
            acc += chunk_total;
        }
        if (lane == 0) s_cut = cut;
    }
    __syncthreads();

    // ---- compact survivors (bin >= cut; rare -> plain atomics) ----
    const int cut = s_cut;
    for (int i = tid; i < NWARP * SEG; i += T1) {
        int w = i / SEG;
        int o = i - w * SEG;
        int c = wcnt[w]; c = (c < SEG) ? c : SEG;
        if (o < c) {
            unsigned long long key = list[i];
            if (bin_of(__uint_as_float((unsigned)(key >> 32))) >= cut) {
                int pos = atomicAdd(&s_sc, 1);
                if (pos < SCAP) surv[pos] = key;
            }
        }
    }
    __syncthreads();

    // ---- warp 0: 30 argmax rounds + subpixel refine ----
    if (tid < 32) {
        const int n = (s_sc < SCAP) ? s_sc : SCAP;
        for (int p = 0; p < Pn; ++p) {
            unsigned long long best = 0ull;
            int bpos = -1;
            for (int i = lane; i < n; i += 32) {
                unsigned long long c = surv[i];
                if (c > best) { best = c; bpos = i; }
            }
            #pragma unroll
            for (int off = 16; off > 0; off >>= 1) {
                unsigned long long ob = __shfl_down_sync(0xffffffffu, best, off);
                int op = __shfl_down_sync(0xffffffffu, bpos, off);
                if (ob > best) { best = ob; bpos = op; }
            }
            best = __shfl_sync(0xffffffffu, best, 0);
            bpos = __shfl_sync(0xffffffffu, bpos, 0);
            if (lane == 0) {
                s_top[p] = best;
                if (bpos >= 0) surv[bpos] = 0ull;
            }
            __syncwarp();
        }

        if (lane < Pn) {
            unsigned long long key = s_top[lane];
            float px = 0.f, py = 0.f, sc = 0.f;
            if (key != 0ull) {
                unsigned idx = 0xFFFFFFFFu - (unsigned)(key & 0xFFFFFFFFu);
                float h = __uint_as_float((unsigned)(key >> 32));
                int y = idx / Wdim;
                int x = idx - y * Wdim;
                float dx = 0.f, dy = 0.f;
                if (y > 0 && y < Hdim - 1 && x > 0 && x < Wdim - 1) {
                    float r = __ldg(hp + idx + 1),    l = __ldg(hp + idx - 1);
                    float d = __ldg(hp + idx + Wdim), u = __ldg(hp + idx - Wdim);
                    float dxr = 0.5f * (r - l);
                    float dxx = (r + l) - 2.0f * h;
                    dx = (fabsf(dxx) > 1e-6f) ? (dxr / (-dxx)) : dxr;
                    float dyr = 0.5f * (d - u);
                    float dyy = (d + u) - 2.0f * h;
                    dy = (fabsf(dyy) > 1e-6f) ? (dyr / (-dyy)) : dyr;
                }
                px = (float)x + dx;
                py = (float)y + dy;
                sc = h;
            }
            float* o = out_peaks + ((size_t)ch * Pn + lane) * 3;
            o[0] = px; o[1] = py; o[2] = sc;
        }
    }
}

// ---------------------------------------------------------------------------
// Stage 2: persistent, 148 blocks (1/SM), each processing ~4 limbs with a
// double-buffered cp.async pipeline: next channel load is issued before
// waiting on the current one, keeping DRAM busy through compute phases.
// ---------------------------------------------------------------------------
__device__ __forceinline__ const float4* chan_ptr(const float* paf, int bl, int c) {
    int b = bl / Ln;
    int l = bl - b * Ln;
    return (const float4*)(paf + ((size_t)b * 38 + 2 * l + c) * HW);
}

__global__ void __launch_bounds__(T2, 1) stage2_kernel(const float* __restrict__ paf,
                                                       const float* __restrict__ peaks,
                                                       float* __restrict__ conn)
{
    extern __shared__ float s2[];
    float* buf0 = s2;        // x channels
    float* buf1 = s2 + HW;   // y channels

    __shared__ float sax[Pn], say[Pn], sas[Pn];
    __shared__ float sbx[Pn], sby[Pn], sbs[Pn];

    const int bid = blockIdx.x;
    const int nlimb = (NBL - 1 - bid) / GRID2 + 1;
    const int tid = threadIdx.x;
    const float step = 1.0f / 9.0f;

    // prologue: x_0 -> buf0, y_0 -> buf1
    {
        const float4* px0 = chan_ptr(paf, bid, 0);
        for (int i = tid; i < NG; i += T2) cp16(&((float4*)buf0)[i], px0 + i);
        cp_commit();
        const float4* py0 = chan_ptr(paf, bid, 1);
        for (int i = tid; i < NG; i += T2) cp16(&((float4*)buf1)[i], py0 + i);
        cp_commit();
    }
    cudaGridDependencySynchronize();     // peaks valid from here on

    for (int w = 0; w < nlimb; ++w) {
        const int bl = bid + w * GRID2;
        const int b = bl / Ln;
        const int l = bl - b * Ln;

        cp_wait<1>();                    // x_w resident (oldest group done)
        // stage peak sets for this limb
        const int ja = c_skel_a[l];
        const int jb = c_skel_b[l];
        if (tid < Pn) {
            const float* pa = peaks + ((size_t)(b * Kdim + ja) * Pn + tid) * 3;
            sax[tid] = pa[0]; say[tid] = pa[1]; sas[tid] = pa[2];
        } else if (tid >= 32 && tid < 32 + Pn) {
            int j = tid - 32;
            const float* pb = peaks + ((size_t)(b * Kdim + jb) * Pn + j) * 3;
            sbx[j] = pb[0]; sby[j] = pb[1]; sbs[j] = pb[2];
        }
        __syncthreads();

        // ---- x phase ----
        int   lin[2][Sn];
        float xp [2][Sn];
        float vyv[2];
        float halfs[2];
        bool  pv[2];

        #pragma unroll
        for (int q = 0; q < 2; ++q) {
            int pr = tid + q * T2;
            bool act = (pr < Pn * Pn);
            int i = act ? (pr / Pn) : 0;
            int j = act ? (pr - i * Pn) : 0;
            float ax = sax[i], ay = say[i], sa = sas[i];
            float bx = sbx[j], by = sby[j], sb = sbs[j];
            bool valid = act && (sa > 0.1f) && (sb > 0.1f);
            pv[q] = valid;
            halfs[q] = 0.5f * (sa + sb);
            float dxl = bx - ax;
            float dyl = by - ay;
            float norm = sqrtf(__fadd_rn(__fmul_rn(dxl, dxl), __fmul_rn(dyl, dyl))) + 1e-8f;
            float vx = dxl / norm;
            float vy = dyl / norm;
            vyv[q] = vy;
            #pragma unroll
            for (int s = 0; s < Sn; ++s) {
                float t = (float)s * step;
                // no-FMA: a ulp flip at a .5 boundary changes the gathered cell
                float xs = __fadd_rn(ax, __fmul_rn(t, dxl));
                float ys = __fadd_rn(ay, __fmul_rn(t, dyl));
                float fx = fminf(fmaxf(rintf(xs), 0.0f), (float)(Wdim - 1));
                float fy = fminf(fmaxf(rintf(ys), 0.0f), (float)(Hdim - 1));
                int li = valid ? ((int)fy * Wdim + (int)fx) : 0;
                lin[q][s] = li;
                xp[q][s] = __fmul_rn(buf0[li], vx);
            }
        }
        __syncthreads();                 // buf0 consumed

        if (w + 1 < nlimb) {             // prefetch x_{w+1} before waiting on y_w
            const float4* nx = chan_ptr(paf, bl + GRID2, 0);
            for (int i = tid; i < NG; i += T2) cp16(&((float4*)buf0)[i], nx + i);
            cp_commit();
            cp_wait<1>();                // y_w done (x_{w+1} may stay pending)
        } else {
            cp_wait<0>();                // y_w done
        }
        __syncthreads();

        // ---- y phase ----
        float* co = conn + (size_t)bl * Pn * Pn;
        #pragma unroll
        for (int q = 0; q < 2; ++q) {
            int pr = tid + q * T2;
            bool act = (pr < Pn * Pn);
            float sum = 0.0f;
            int c = 0;
            #pragma unroll
            for (int s = 0; s < Sn; ++s) {
                float v = __fadd_rn(xp[q][s], __fmul_rn(buf1[lin[q][s]], vyv[q]));
                sum = __fadd_rn(sum, v);
                c += (v > 0.05f) ? 1 : 0;
            }
            float outv = 0.0f;
            if (pv[q]) {
                float mean = sum / 10.0f;
                float ratio = (float)c / 10.0f;
                if (mean > 0.0f && ratio > 0.8f)
                    outv = mean + halfs[q];
            }
            if (act) co[pr] = outv;
        }
        __syncthreads();                 // buf1 consumed

        if (w + 1 < nlimb) {             // prefetch y_{w+1}
            const float4* ny = chan_ptr(paf, bl + GRID2, 1);
            for (int i = tid; i < NG; i += T2) cp16(&((float4*)buf1)[i], ny + i);
            cp_commit();
        }
    }
}

// ---------------------------------------------------------------------------
extern "C" void kernel_launch(void* const* d_in, const int* in_sizes, int n_in,
                              void* d_out, int out_size)
{
    const float* heat = (const float*)d_in[0];
    const float* paf  = (const float*)d_in[1];
    float* out   = (float*)d_out;
    float* peaks = out;                                  // B*K*P*3 = 48960
    float* conn  = out + (size_t)Bdim * Kdim * Pn * 3;   // B*L*P*P = 547200

    const int smem2 = 2 * HW * 4;                        // 204800 (1 block/SM)
    cudaFuncSetAttribute(stage2_kernel, cudaFuncAttributeMaxDynamicSharedMemorySize, smem2);

    stage1_kernel<<<NCH, T1>>>(heat, peaks);

    cudaLaunchConfig_t cfg = {};
    cfg.gridDim = dim3(GRID2);
    cfg.blockDim = dim3(T2);
    cfg.dynamicSmemBytes = smem2;
    cfg.stream = 0;
    cudaLaunchAttribute attrs[1];
    attrs[0].id = cudaLaunchAttributeProgrammaticStreamSerialization;
    attrs[0].val.programmaticStreamSerializationAllowed = 1;
    cfg.attrs = attrs;
    cfg.numAttrs = 1;
    cudaLaunchKernelEx(&cfg, stage2_kernel, paf, (const float*)peaks, conn);
}

// round 12
// speedup vs baseline: 1.1447x; 1.1447x over previous
#include <cuda_runtime.h>
#include <cstdint>

#define Bdim 32
#define Kdim 17
#define Hdim 160
#define Wdim 160
#define HW   (Hdim*Wdim)
#define NG   (HW/4)
#define Pn   30
#define Sn   10
#define Ln   19
#define NCH  (Bdim*Kdim)
#define T1   320
#define NWARP (T1/32)
#define NSTRIP 20
#define SPX   8
#define RPB   10
#define SEG   384
#define T2   512
#define NBINS 1024
#define SCAP  256
#define NEGF  (-1.0e30f)

__constant__ int c_skel_a[Ln] = {15,13,16,14,11, 5, 6, 5, 5, 6, 7, 8, 1, 0, 0, 1, 2, 3, 4};
__constant__ int c_skel_b[Ln] = {13,11,14,12,12,11,12, 6, 7, 8, 9,10, 2, 1, 2, 3, 4, 5, 6};

// ---------------- cp.async helpers ----------------
__device__ __forceinline__ void cp16(void* s, const void* g) {
    unsigned sa = (unsigned)__cvta_generic_to_shared(s);
    asm volatile("cp.async.cg.shared.global [%0], [%1], 16;\n" :: "r"(sa), "l"(g));
}
__device__ __forceinline__ void cp_commit() { asm volatile("cp.async.commit_group;\n"); }
template <int N>
__device__ __forceinline__ void cp_wait() { asm volatile("cp.async.wait_group %0;\n" :: "n"(N)); }

// monotone bin: v = h^9 (uniform-izes max-of-9 peak-score distribution)
__device__ __forceinline__ int bin_of(float h) {
    float h2 = h * h;
    float h4 = h2 * h2;
    float v  = h4 * h4 * h;
    int b = (int)(v * (float)NBINS);
    return b < 0 ? 0 : (b > NBINS - 1 ? NBINS - 1 : b);
}

__device__ __forceinline__ float max3(float a, float b, float c) {
    return fmaxf(fmaxf(a, b), c);
}

// load one row of an 8px strip: 2 contiguous float4 + 2 edge scalars.
__device__ __forceinline__ void loadrow8(const float* __restrict__ hp,
                                         int y, int x0, bool lf, bool rt,
                                         float rm[8], float px[8])
{
    if (y < 0 || y >= Hdim) {
        #pragma unroll
        for (int j = 0; j < SPX; ++j) { rm[j] = NEGF; px[j] = NEGF; }
        return;
    }
    const float4* p4 = (const float4*)(hp + y * Wdim + x0);
    float4 A = __ldg(p4);
    float4 B = __ldg(p4 + 1);
    float w[SPX + 2];
    w[0] = lf ? __ldg(hp + y * Wdim + x0 - 1) : NEGF;
    w[1] = A.x; w[2] = A.y; w[3] = A.z; w[4] = A.w;
    w[5] = B.x; w[6] = B.y; w[7] = B.z; w[8] = B.w;
    w[9] = rt ? __ldg(hp + y * Wdim + x0 + SPX) : NEGF;
    #pragma unroll
    for (int j = 0; j < SPX; ++j) {
        px[j] = w[j + 1];
        rm[j] = max3(w[j], w[j + 1], w[j + 2]);
    }
}

// ---------------------------------------------------------------------------
// Stage 1: one block per (b,k) channel.  Strip sweep (8px x 10row register
// window) + per-warp segmented candidate lists (parallel ATOMS counters),
// histogram radix-select, warp argmax, subpixel refine.
// ---------------------------------------------------------------------------
__global__ void __launch_bounds__(T1) stage1_kernel(const float* __restrict__ heat,
                                                    float* __restrict__ out_peaks)
{
    if (threadIdx.x == 0) cudaTriggerProgrammaticLaunchCompletion();

    __shared__ unsigned long long list[NWARP * SEG];
    __shared__ int wcnt[NWARP];
    __shared__ unsigned hist[NBINS];
    __shared__ unsigned long long surv[SCAP];
    __shared__ unsigned long long s_top[Pn];
    __shared__ int s_sc, s_cut;

    const int ch = blockIdx.x;
    const float* hp = heat + (size_t)ch * HW;
    const int tid = threadIdx.x;
    const int wid = tid >> 5;
    const int lane = tid & 31;

    for (int i = tid; i < NBINS; i += T1) hist[i] = 0;
    if (tid < NWARP) wcnt[tid] = 0;
    if (tid == 0) { s_sc = 0; s_cut = 0; }
    __syncthreads();

    // ---- pass 1: strip sweep (20 strips x 16 bands, 8px x 10row strips) ----
    const int strip = tid % NSTRIP;
    const int band  = tid / NSTRIP;
    const int x0 = strip * SPX;
    const int y0 = band * RPB;
    const bool lf = (strip > 0);
    const bool rt = (strip < NSTRIP - 1);

    float rmU[SPX], rmC[SPX], rmD[SPX];
    float C8[SPX], D8[SPX];

    loadrow8(hp, y0 - 1, x0, lf, rt, rmU, D8);
    loadrow8(hp, y0,     x0, lf, rt, rmC, C8);

    #pragma unroll 2
    for (int r = 0; r < RPB; ++r) {
        const int y = y0 + r;
        loadrow8(hp, y + 1, x0, lf, rt, rmD, D8);
        #pragma unroll
        for (int j = 0; j < SPX; ++j) {
            float h = C8[j];
            if (h > 0.1f && h >= rmU[j] && h >= rmC[j] && h >= rmD[j]) {
                int pos = atomicAdd(&wcnt[wid], 1);
                if (pos < SEG) {
                    unsigned idx = (unsigned)(y * Wdim + x0 + j);
                    list[wid * SEG + pos] = ((unsigned long long)__float_as_uint(h) << 32) |
                                            (unsigned long long)(0xFFFFFFFFu - idx);
                }
            }
        }
        #pragma unroll
        for (int j = 0; j < SPX; ++j) {
            rmU[j] = rmC[j]; rmC[j] = rmD[j]; C8[j] = D8[j];
        }
    }
    __syncthreads();

    // ---- histogram over segmented candidate lists ----
    for (int i = tid; i < NWARP * SEG; i += T1) {
        int w = i / SEG;
        int o = i - w * SEG;
        int c = wcnt[w]; c = (c < SEG) ? c : SEG;
        if (o < c) {
            float h = __uint_as_float((unsigned)(list[i] >> 32));
            atomicAdd(&hist[bin_of(h)], 1u);
        }
    }
    __syncthreads();

    // ---- warp 0: cutoff bin = highest bin whose suffix count >= Pn ----
    if (tid < 32) {
        int acc = 0, cut = 0;
        for (int base = NBINS - 32; base >= 0; base -= 32) {
            int s = (int)hist[base + lane];
            #pragma unroll
            for (int off = 1; off < 32; off <<= 1) {
                int t = __shfl_down_sync(0xffffffffu, s, off);
                if (lane + off < 32) s += t;
            }
            int chunk_total = __shfl_sync(0xffffffffu, s, 0);
            if (acc + chunk_total >= Pn) {
                unsigned msk = __ballot_sync(0xffffffffu, acc + s >= Pn);
                cut = base + (31 - __clz(msk));
                break;
            }
            acc += chunk_total;
        }
        if (lane == 0) s_cut = cut;
    }
    __syncthreads();

    // ---- compact survivors (bin >= cut; rare -> plain atomics) ----
    const int cut = s_cut;
    for (int i = tid; i < NWARP * SEG; i += T1) {
        int w = i / SEG;
        int o = i - w * SEG;
        int c = wcnt[w]; c = (c < SEG) ? c : SEG;
        if (o < c) {
            unsigned long long key = list[i];
            if (bin_of(__uint_as_float((unsigned)(key >> 32))) >= cut) {
                int pos = atomicAdd(&s_sc, 1);
                if (pos < SCAP) surv[pos] = key;
            }
        }
    }
    __syncthreads();

    // ---- warp 0: 30 argmax rounds + subpixel refine ----
    if (tid < 32) {
        const int n = (s_sc < SCAP) ? s_sc : SCAP;
        for (int p = 0; p < Pn; ++p) {
            unsigned long long best = 0ull;
            int bpos = -1;
            for (int i = lane; i < n; i += 32) {
                unsigned long long c = surv[i];
                if (c > best) { best = c; bpos = i; }
            }
            #pragma unroll
            for (int off = 16; off > 0; off >>= 1) {
                unsigned long long ob = __shfl_down_sync(0xffffffffu, best, off);
                int op = __shfl_down_sync(0xffffffffu, bpos, off);
                if (ob > best) { best = ob; bpos = op; }
            }
            best = __shfl_sync(0xffffffffu, best, 0);
            bpos = __shfl_sync(0xffffffffu, bpos, 0);
            if (lane == 0) {
                s_top[p] = best;
                if (bpos >= 0) surv[bpos] = 0ull;
            }
            __syncwarp();
        }

        if (lane < Pn) {
            unsigned long long key = s_top[lane];
            float px = 0.f, py = 0.f, sc = 0.f;
            if (key != 0ull) {
                unsigned idx = 0xFFFFFFFFu - (unsigned)(key & 0xFFFFFFFFu);
                float h = __uint_as_float((unsigned)(key >> 32));
                int y = idx / Wdim;
                int x = idx - y * Wdim;
                float dx = 0.f, dy = 0.f;
                if (y > 0 && y < Hdim - 1 && x > 0 && x < Wdim - 1) {
                    float r = __ldg(hp + idx + 1),    l = __ldg(hp + idx - 1);
                    float d = __ldg(hp + idx + Wdim), u = __ldg(hp + idx - Wdim);
                    float dxr = 0.5f * (r - l);
                    float dxx = (r + l) - 2.0f * h;
                    dx = (fabsf(dxx) > 1e-6f) ? (dxr / (-dxx)) : dxr;
                    float dyr = 0.5f * (d - u);
                    float dyy = (d + u) - 2.0f * h;
                    dy = (fabsf(dyy) > 1e-6f) ? (dyr / (-dyy)) : dyr;
                }
                px = (float)x + dx;
                py = (float)y + dy;
                sc = h;
            }
            float* o = out_peaks + ((size_t)ch * Pn + lane) * 3;
            o[0] = px; o[1] = py; o[2] = sc;
        }
    }
}

// ---------------------------------------------------------------------------
// Stage 2 (R10 proven version): per-(b,l) limb, one PAF channel in smem at a
// time (100KB) so two blocks co-reside per SM; PDL overlaps the PAF-x
// prologue with stage1.
// ---------------------------------------------------------------------------
__global__ void __launch_bounds__(T2, 2) stage2_kernel(const float* __restrict__ paf,
                                                       const float* __restrict__ peaks,
                                                       float* __restrict__ conn)
{
    extern __shared__ float s2[];                // HW floats (reused x then y)

    __shared__ float sax[Pn], say[Pn], sas[Pn];
    __shared__ float sbx[Pn], sby[Pn], sbs[Pn];

    const int bl = blockIdx.x;      // b*Ln + l
    const int b = bl / Ln;
    const int l = bl - b * Ln;

    const float4* gx = (const float4*)(paf + ((size_t)b * 38 + 2 * l) * HW);
    const float4* gy = (const float4*)(paf + ((size_t)b * 38 + 2 * l + 1) * HW);

    for (int i = threadIdx.x; i < NG; i += T2)
        cp16(&((float4*)s2)[i], &gx[i]);
    cp_commit();

    cudaGridDependencySynchronize();

    const int ja = c_skel_a[l];
    const int jb = c_skel_b[l];
    if (threadIdx.x < Pn) {
        const float* pa = peaks + ((size_t)(b * Kdim + ja) * Pn + threadIdx.x) * 3;
        sax[threadIdx.x] = pa[0]; say[threadIdx.x] = pa[1]; sas[threadIdx.x] = pa[2];
    } else if (threadIdx.x >= 32 && threadIdx.x < 32 + Pn) {
        int j = threadIdx.x - 32;
        const float* pb = peaks + ((size_t)(b * Kdim + jb) * Pn + j) * 3;
        sbx[j] = pb[0]; sby[j] = pb[1]; sbs[j] = pb[2];
    }

    cp_wait<0>();
    __syncthreads();

    int   lin[2][Sn];
    float xp [2][Sn];
    float vyv[2];
    float halfs[2];
    bool  pv[2];
    const float step = 1.0f / 9.0f;

    #pragma unroll
    for (int q = 0; q < 2; ++q) {
        int pr = threadIdx.x + q * T2;
        bool act = (pr < Pn * Pn);
        int i = act ? (pr / Pn) : 0;
        int j = act ? (pr - i * Pn) : 0;
        float ax = sax[i], ay = say[i], sa = sas[i];
        float bx = sbx[j], by = sby[j], sb = sbs[j];
        bool valid = act && (sa > 0.1f) && (sb > 0.1f);
        pv[q] = valid;
        halfs[q] = 0.5f * (sa + sb);
        float dxl = bx - ax;
        float dyl = by - ay;
        float norm = sqrtf(__fadd_rn(__fmul_rn(dxl, dxl), __fmul_rn(dyl, dyl))) + 1e-8f;
        float vx = dxl / norm;
        float vy = dyl / norm;
        vyv[q] = vy;
        #pragma unroll
        for (int s = 0; s < Sn; ++s) {
            float t = (float)s * step;
            // no-FMA: a ulp flip at a .5 boundary changes the gathered cell
            float xs = __fadd_rn(ax, __fmul_rn(t, dxl));
            float ys = __fadd_rn(ay, __fmul_rn(t, dyl));
            float fx = fminf(fmaxf(rintf(xs), 0.0f), (float)(Wdim - 1));
            float fy = fminf(fmaxf(rintf(ys), 0.0f), (float)(Hdim - 1));
            int li = valid ? ((int)fy * Wdim + (int)fx) : 0;
            lin[q][s] = li;
            xp[q][s] = __fmul_rn(s2[li], vx);
        }
    }
    __syncthreads();                 // all pafx reads done; buffer free

    for (int i = threadIdx.x; i < NG; i += T2)
        cp16(&((float4*)s2)[i], &gy[i]);
    cp_commit();
    cp_wait<0>();
    __syncthreads();

    float* co = conn + (size_t)bl * Pn * Pn;
    #pragma unroll
    for (int q = 0; q < 2; ++q) {
        int pr = threadIdx.x + q * T2;
        bool act = (pr < Pn * Pn);
        float sum = 0.0f;
        int c = 0;
        #pragma unroll
        for (int s = 0; s < Sn; ++s) {
            float v = __fadd_rn(xp[q][s], __fmul_rn(s2[lin[q][s]], vyv[q]));
            sum = __fadd_rn(sum, v);
            c += (v > 0.05f) ? 1 : 0;
        }
        float outv = 0.0f;
        if (pv[q]) {
            float mean = sum / 10.0f;
            float ratio = (float)c / 10.0f;
            if (mean > 0.0f && ratio > 0.8f)
                outv = mean + halfs[q];
        }
        if (act) co[pr] = outv;
    }
}

// ---------------------------------------------------------------------------
extern "C" void kernel_launch(void* const* d_in, const int* in_sizes, int n_in,
                              void* d_out, int out_size)
{
    const float* heat = (const float*)d_in[0];
    const float* paf  = (const float*)d_in[1];
    float* out   = (float*)d_out;
    float* peaks = out;                                  // B*K*P*3 = 48960
    float* conn  = out + (size_t)Bdim * Kdim * Pn * 3;   // B*L*P*P = 547200

    const int smem2 = HW * 4;                            // 102400 -> 2 blocks/SM
    cudaFuncSetAttribute(stage2_kernel, cudaFuncAttributeMaxDynamicSharedMemorySize, smem2);

    stage1_kernel<<<NCH, T1>>>(heat, peaks);

    cudaLaunchConfig_t cfg = {};
    cfg.gridDim = dim3(Bdim * Ln);
    cfg.blockDim = dim3(T2);
    cfg.dynamicSmemBytes = smem2;
    cfg.stream = 0;
    cudaLaunchAttribute attrs[1];
    attrs[0].id = cudaLaunchAttributeProgrammaticStreamSerialization;
    attrs[0].val.programmaticStreamSerializationAllowed = 1;
    cfg.attrs = attrs;
    cfg.numAttrs = 1;
    cudaLaunchKernelEx(&cfg, stage2_kernel, paf, (const float*)peaks, conn);
}

// round 13
// speedup vs baseline: 1.1831x; 1.0335x over previous
#include <cuda_runtime.h>
#include <cstdint>

#define Bdim 32
#define Kdim 17
#define Hdim 160
#define Wdim 160
#define HW   (Hdim*Wdim)
#define NG   (HW/4)
#define Pn   30
#define Sn   10
#define Ln   19
#define NCH  (Bdim*Kdim)
#define T1   320
#define NSTRIP 20
#define SPX   8
#define RPB   10
#define SLOTS 16
#define OVCAP 256
#define T2   512
#define NBINS 1024
#define SCAP  256
#define NEGF  (-1.0e30f)

__constant__ int c_skel_a[Ln] = {15,13,16,14,11, 5, 6, 5, 5, 6, 7, 8, 1, 0, 0, 1, 2, 3, 4};
__constant__ int c_skel_b[Ln] = {13,11,14,12,12,11,12, 6, 7, 8, 9,10, 2, 1, 2, 3, 4, 5, 6};

// ---------------- cp.async helpers ----------------
__device__ __forceinline__ void cp16(void* s, const void* g) {
    unsigned sa = (unsigned)__cvta_generic_to_shared(s);
    asm volatile("cp.async.cg.shared.global [%0], [%1], 16;\n" :: "r"(sa), "l"(g));
}
__device__ __forceinline__ void cp_commit() { asm volatile("cp.async.commit_group;\n"); }
template <int N>
__device__ __forceinline__ void cp_wait() { asm volatile("cp.async.wait_group %0;\n" :: "n"(N)); }

// monotone bin: v = h^9 (uniform-izes max-of-9 peak-score distribution)
__device__ __forceinline__ int bin_of(float h) {
    float h2 = h * h;
    float h4 = h2 * h2;
    float v  = h4 * h4 * h;
    int b = (int)(v * (float)NBINS);
    return b < 0 ? 0 : (b > NBINS - 1 ? NBINS - 1 : b);
}

__device__ __forceinline__ float max3(float a, float b, float c) {
    return fmaxf(fmaxf(a, b), c);
}

// load one row of an 8px strip: 2 contiguous float4 + 2 edge scalars.
__device__ __forceinline__ void loadrow8(const float* __restrict__ hp,
                                         int y, int x0, bool lf, bool rt,
                                         float rm[8], float px[8])
{
    if (y < 0 || y >= Hdim) {
        #pragma unroll
        for (int j = 0; j < SPX; ++j) { rm[j] = NEGF; px[j] = NEGF; }
        return;
    }
    const float4* p4 = (const float4*)(hp + y * Wdim + x0);
    float4 A = __ldg(p4);
    float4 B = __ldg(p4 + 1);
    float w[SPX + 2];
    w[0] = lf ? __ldg(hp + y * Wdim + x0 - 1) : NEGF;
    w[1] = A.x; w[2] = A.y; w[3] = A.z; w[4] = A.w;
    w[5] = B.x; w[6] = B.y; w[7] = B.z; w[8] = B.w;
    w[9] = rt ? __ldg(hp + y * Wdim + x0 + SPX) : NEGF;
    #pragma unroll
    for (int j = 0; j < SPX; ++j) {
        px[j] = w[j + 1];
        rm[j] = max3(w[j], w[j + 1], w[j + 2]);
    }
}

// ---------------------------------------------------------------------------
// Stage 1: one block per (b,k) channel.  Strip sweep; hits go to PRIVATE
// per-thread smem slots (no atomics; interleaved layout = conflict-free);
// rare overflow spills to a tiny shared list.  Then histogram radix-select
// + warp argmax + subpixel refine.
// ---------------------------------------------------------------------------
__global__ void __launch_bounds__(T1) stage1_kernel(const float* __restrict__ heat,
                                                    float* __restrict__ out_peaks)
{
    if (threadIdx.x == 0) cudaTriggerProgrammaticLaunchCompletion();

    __shared__ unsigned long long slots[SLOTS * T1];   // slots[k*T1 + tid]
    __shared__ unsigned long long ov[OVCAP];
    __shared__ unsigned hist[NBINS];
    __shared__ unsigned long long surv[SCAP];
    __shared__ unsigned long long s_top[Pn];
    __shared__ int s_ov, s_sc, s_cut;

    const int ch = blockIdx.x;
    const float* hp = heat + (size_t)ch * HW;
    const int tid = threadIdx.x;
    const int lane = tid & 31;

    for (int i = tid; i < NBINS; i += T1) hist[i] = 0;
    if (tid == 0) { s_ov = 0; s_sc = 0; s_cut = 0; }
    __syncthreads();

    // ---- pass 1: strip sweep (20 strips x 16 bands, 8px x 10row strips) ----
    const int strip = tid % NSTRIP;
    const int band  = tid / NSTRIP;
    const int x0 = strip * SPX;
    const int y0 = band * RPB;
    const bool lf = (strip > 0);
    const bool rt = (strip < NSTRIP - 1);

    float rmU[SPX], rmC[SPX], rmD[SPX];
    float C8[SPX], D8[SPX];
    int cnt = 0;

    loadrow8(hp, y0 - 1, x0, lf, rt, rmU, D8);
    loadrow8(hp, y0,     x0, lf, rt, rmC, C8);

    #pragma unroll 2
    for (int r = 0; r < RPB; ++r) {
        const int y = y0 + r;
        loadrow8(hp, y + 1, x0, lf, rt, rmD, D8);
        #pragma unroll
        for (int j = 0; j < SPX; ++j) {
            float h = C8[j];
            if (h > 0.1f && h >= rmU[j] && h >= rmC[j] && h >= rmD[j]) {
                unsigned idx = (unsigned)(y * Wdim + x0 + j);
                unsigned long long key =
                    ((unsigned long long)__float_as_uint(h) << 32) |
                    (unsigned long long)(0xFFFFFFFFu - idx);
                if (cnt < SLOTS) {
                    slots[cnt * T1 + tid] = key;
                    ++cnt;
                } else {                       // rare spill
                    int pos = atomicAdd(&s_ov, 1);
                    if (pos < OVCAP) ov[pos] = key;
                }
            }
        }
        #pragma unroll
        for (int j = 0; j < SPX; ++j) {
            rmU[j] = rmC[j]; rmC[j] = rmD[j]; C8[j] = D8[j];
        }
    }
    __syncthreads();

    // ---- histogram: each thread walks its own slots + strided overflow ----
    for (int k = 0; k < cnt; ++k) {
        float h = __uint_as_float((unsigned)(slots[k * T1 + tid] >> 32));
        atomicAdd(&hist[bin_of(h)], 1u);
    }
    {
        int ovn = s_ov; ovn = (ovn < OVCAP) ? ovn : OVCAP;
        for (int i = tid; i < ovn; i += T1) {
            float h = __uint_as_float((unsigned)(ov[i] >> 32));
            atomicAdd(&hist[bin_of(h)], 1u);
        }
    }
    __syncthreads();

    // ---- warp 0: cutoff bin = highest bin whose suffix count >= Pn ----
    if (tid < 32) {
        int acc = 0, cut = 0;
        for (int base = NBINS - 32; base >= 0; base -= 32) {
            int s = (int)hist[base + lane];
            #pragma unroll
            for (int off = 1; off < 32; off <<= 1) {
                int t = __shfl_down_sync(0xffffffffu, s, off);
                if (lane + off < 32) s += t;
            }
            int chunk_total = __shfl_sync(0xffffffffu, s, 0);
            if (acc + chunk_total >= Pn) {
                unsigned msk = __ballot_sync(0xffffffffu, acc + s >= Pn);
                cut = base + (31 - __clz(msk));
                break;
            }
            acc += chunk_total;
        }
        if (lane == 0) s_cut = cut;
    }
    __syncthreads();

    // ---- compact survivors (bin >= cut; ~33/block -> negligible atomics) ----
    const int cut = s_cut;
    for (int k = 0; k < cnt; ++k) {
        unsigned long long key = slots[k * T1 + tid];
        if (bin_of(__uint_as_float((unsigned)(key >> 32))) >= cut) {
            int pos = atomicAdd(&s_sc, 1);
            if (pos < SCAP) surv[pos] = key;
        }
    }
    {
        int ovn = s_ov; ovn = (ovn < OVCAP) ? ovn : OVCAP;
        for (int i = tid; i < ovn; i += T1) {
            unsigned long long key = ov[i];
            if (bin_of(__uint_as_float((unsigned)(key >> 32))) >= cut) {
                int pos = atomicAdd(&s_sc, 1);
                if (pos < SCAP) surv[pos] = key;
            }
        }
    }
    __syncthreads();

    // ---- warp 0: 30 argmax rounds + subpixel refine ----
    if (tid < 32) {
        const int n = (s_sc < SCAP) ? s_sc : SCAP;
        for (int p = 0; p < Pn; ++p) {
            unsigned long long best = 0ull;
            int bpos = -1;
            for (int i = lane; i < n; i += 32) {
                unsigned long long c = surv[i];
                if (c > best) { best = c; bpos = i; }
            }
            #pragma unroll
            for (int off = 16; off > 0; off >>= 1) {
                unsigned long long ob = __shfl_down_sync(0xffffffffu, best, off);
                int op = __shfl_down_sync(0xffffffffu, bpos, off);
                if (ob > best) { best = ob; bpos = op; }
            }
            best = __shfl_sync(0xffffffffu, best, 0);
            bpos = __shfl_sync(0xffffffffu, bpos, 0);
            if (lane == 0) {
                s_top[p] = best;
                if (bpos >= 0) surv[bpos] = 0ull;
            }
            __syncwarp();
        }

        if (lane < Pn) {
            unsigned long long key = s_top[lane];
            float px = 0.f, py = 0.f, sc = 0.f;
            if (key != 0ull) {
                unsigned idx = 0xFFFFFFFFu - (unsigned)(key & 0xFFFFFFFFu);
                float h = __uint_as_float((unsigned)(key >> 32));
                int y = idx / Wdim;
                int x = idx - y * Wdim;
                float dx = 0.f, dy = 0.f;
                if (y > 0 && y < Hdim - 1 && x > 0 && x < Wdim - 1) {
                    float r = __ldg(hp + idx + 1),    l = __ldg(hp + idx - 1);
                    float d = __ldg(hp + idx + Wdim), u = __ldg(hp + idx - Wdim);
                    float dxr = 0.5f * (r - l);
                    float dxx = (r + l) - 2.0f * h;
                    dx = (fabsf(dxx) > 1e-6f) ? (dxr / (-dxx)) : dxr;
                    float dyr = 0.5f * (d - u);
                    float dyy = (d + u) - 2.0f * h;
                    dy = (fabsf(dyy) > 1e-6f) ? (dyr / (-dyy)) : dyr;
                }
                px = (float)x + dx;
                py = (float)y + dy;
                sc = h;
            }
            float* o = out_peaks + ((size_t)ch * Pn + lane) * 3;
            o[0] = px; o[1] = py; o[2] = sc;
        }
    }
}

// ---------------------------------------------------------------------------
// Stage 2 (R10 proven version): per-(b,l) limb, one PAF channel in smem at a
// time (100KB) so two blocks co-reside per SM; PDL overlaps the PAF-x
// prologue with stage1.
// ---------------------------------------------------------------------------
__global__ void __launch_bounds__(T2, 2) stage2_kernel(const float* __restrict__ paf,
                                                       const float* __restrict__ peaks,
                                                       float* __restrict__ conn)
{
    extern __shared__ float s2[];                // HW floats (reused x then y)

    __shared__ float sax[Pn], say[Pn], sas[Pn];
    __shared__ float sbx[Pn], sby[Pn], sbs[Pn];

    const int bl = blockIdx.x;      // b*Ln + l
    const int b = bl / Ln;
    const int l = bl - b * Ln;

    const float4* gx = (const float4*)(paf + ((size_t)b * 38 + 2 * l) * HW);
    const float4* gy = (const float4*)(paf + ((size_t)b * 38 + 2 * l + 1) * HW);

    for (int i = threadIdx.x; i < NG; i += T2)
        cp16(&((float4*)s2)[i], &gx[i]);
    cp_commit();

    cudaGridDependencySynchronize();

    const int ja = c_skel_a[l];
    const int jb = c_skel_b[l];
    if (threadIdx.x < Pn) {
        const float* pa = peaks + ((size_t)(b * Kdim + ja) * Pn + threadIdx.x) * 3;
        sax[threadIdx.x] = pa[0]; say[threadIdx.x] = pa[1]; sas[threadIdx.x] = pa[2];
    } else if (threadIdx.x >= 32 && threadIdx.x < 32 + Pn) {
        int j = threadIdx.x - 32;
        const float* pb = peaks + ((size_t)(b * Kdim + jb) * Pn + j) * 3;
        sbx[j] = pb[0]; sby[j] = pb[1]; sbs[j] = pb[2];
    }

    cp_wait<0>();
    __syncthreads();

    int   lin[2][Sn];
    float xp [2][Sn];
    float vyv[2];
    float halfs[2];
    bool  pv[2];
    const float step = 1.0f / 9.0f;

    #pragma unroll
    for (int q = 0; q < 2; ++q) {
        int pr = threadIdx.x + q * T2;
        bool act = (pr < Pn * Pn);
        int i = act ? (pr / Pn) : 0;
        int j = act ? (pr - i * Pn) : 0;
        float ax = sax[i], ay = say[i], sa = sas[i];
        float bx = sbx[j], by = sby[j], sb = sbs[j];
        bool valid = act && (sa > 0.1f) && (sb > 0.1f);
        pv[q] = valid;
        halfs[q] = 0.5f * (sa + sb);
        float dxl = bx - ax;
        float dyl = by - ay;
        float norm = sqrtf(__fadd_rn(__fmul_rn(dxl, dxl), __fmul_rn(dyl, dyl))) + 1e-8f;
        float vx = dxl / norm;
        float vy = dyl / norm;
        vyv[q] = vy;
        #pragma unroll
        for (int s = 0; s < Sn; ++s) {
            float t = (float)s * step;
            // no-FMA: a ulp flip at a .5 boundary changes the gathered cell
            float xs = __fadd_rn(ax, __fmul_rn(t, dxl));
            float ys = __fadd_rn(ay, __fmul_rn(t, dyl));
            float fx = fminf(fmaxf(rintf(xs), 0.0f), (float)(Wdim - 1));
            float fy = fminf(fmaxf(rintf(ys), 0.0f), (float)(Hdim - 1));
            int li = valid ? ((int)fy * Wdim + (int)fx) : 0;
            lin[q][s] = li;
            xp[q][s] = __fmul_rn(s2[li], vx);
        }
    }
    __syncthreads();                 // all pafx reads done; buffer free

    for (int i = threadIdx.x; i < NG; i += T2)
        cp16(&((float4*)s2)[i], &gy[i]);
    cp_commit();
    cp_wait<0>();
    __syncthreads();

    float* co = conn + (size_t)bl * Pn * Pn;
    #pragma unroll
    for (int q = 0; q < 2; ++q) {
        int pr = threadIdx.x + q * T2;
        bool act = (pr < Pn * Pn);
        float sum = 0.0f;
        int c = 0;
        #pragma unroll
        for (int s = 0; s < Sn; ++s) {
            float v = __fadd_rn(xp[q][s], __fmul_rn(s2[lin[q][s]], vyv[q]));
            sum = __fadd_rn(sum, v);
            c += (v > 0.05f) ? 1 : 0;
        }
        float outv = 0.0f;
        if (pv[q]) {
            float mean = sum / 10.0f;
            float ratio = (float)c / 10.0f;
            if (mean > 0.0f && ratio > 0.8f)
                outv = mean + halfs[q];
        }
        if (act) co[pr] = outv;
    }
}

// ---------------------------------------------------------------------------
extern "C" void kernel_launch(void* const* d_in, const int* in_sizes, int n_in,
                              void* d_out, int out_size)
{
    const float* heat = (const float*)d_in[0];
    const float* paf  = (const float*)d_in[1];
    float* out   = (float*)d_out;
    float* peaks = out;                                  // B*K*P*3 = 48960
    float* conn  = out + (size_t)Bdim * Kdim * Pn * 3;   // B*L*P*P = 547200

    const int smem2 = HW * 4;                            // 102400 -> 2 blocks/SM
    cudaFuncSetAttribute(stage2_kernel, cudaFuncAttributeMaxDynamicSharedMemorySize, smem2);

    stage1_kernel<<<NCH, T1>>>(heat, peaks);

    cudaLaunchConfig_t cfg = {};
    cfg.gridDim = dim3(Bdim * Ln);
    cfg.blockDim = dim3(T2);
    cfg.dynamicSmemBytes = smem2;
    cfg.stream = 0;
    cudaLaunchAttribute attrs[1];
    attrs[0].id = cudaLaunchAttributeProgrammaticStreamSerialization;
    attrs[0].val.programmaticStreamSerializationAllowed = 1;
    cfg.attrs = attrs;
    cfg.numAttrs = 1;
    cudaLaunchKernelEx(&cfg, stage2_kernel, paf, (const float*)peaks, conn);
}